// round 9
// baseline (speedup 1.0000x reference)
#include <cuda_runtime.h>
#include <cuda_bf16.h>
#include <cstdint>

// Problem shape (fixed by reference)
#define PN 8
#define PH 32
#define PL 512
#define PS 512
#define PLS (PL * PS)
#define MAXP 100
#define TPAD 36           // row stride: 16B-aligned rows -> LDS.128 gathers

__global__ __launch_bounds__(256, 4)
void gpe_kernel(const float* __restrict__ QK,
                const int* __restrict__ pos,
                const float* __restrict__ table,
                float* __restrict__ out) {
    __shared__ float t_sh[MAXP * TPAD];  // t_sh[p*36 + h]

    const int bid = blockIdx.x;          // n*PL + l  (one (n,l) row per block)
    const int n = bid >> 9;
    const int l = bid & (PL - 1);
    const int tid = threadIdx.x;

    // Thread owns one s4 (4 consecutive s) and 16 CONTIGUOUS heads.
    const int s4 = tid & 127;
    const int hq = tid >> 7;             // 0 or 1 -> heads hq*16 .. hq*16+15

    // Issue pos load FIRST so it overlaps the table staging below.
    const int4 pp = __ldg(reinterpret_cast<const int4*>(
        pos + ((size_t)n * PL + l) * PS) + s4);

    // Stage table: 800 float4 covering [100][32] row-major; row 0 zeroed.
    const float4* table4 = reinterpret_cast<const float4*>(table);
    #pragma unroll
    for (int i = tid; i < (MAXP * PH) / 4; i += 256) {
        const int p  = i >> 3;
        const int h4 = (i & 7) << 2;
        float4 v = __ldg(table4 + i);
        if (p == 0) { v.x = 0.f; v.y = 0.f; v.z = 0.f; v.w = 0.f; }
        *reinterpret_cast<float4*>(&t_sh[p * TPAD + h4]) = v;
    }

    // Gather row bases (float index); rows are 16B-aligned (36*4 % 16 == 0)
    const int px = pp.x * TPAD;
    const int py = pp.y * TPAD;
    const int pz = pp.z * TPAD;
    const int pw = pp.w * TPAD;

    __syncthreads();

    const size_t base = ((size_t)n * PH + hq * 16) * (size_t)PLS
                      + (size_t)l * PS + ((size_t)s4 << 2);

    // Two bursts of 8 heads. Loads batched 8-deep (MLP), bias gathered with
    // vector LDS.128 (4 contiguous heads per gather), then streamed out.
    #pragma unroll
    for (int half = 0; half < 2; half++) {
        const size_t b0 = base + (size_t)(half * 8) * PLS;
        float4 q[8];
        #pragma unroll
        for (int j = 0; j < 8; j++) {
            q[j] = __ldcs(reinterpret_cast<const float4*>(
                QK + b0 + (size_t)j * PLS));
        }

        const int habs = hq * 16 + half * 8;   // first head of this burst
        #pragma unroll
        for (int g = 0; g < 2; g++) {
            const int hoff = habs + g * 4;
            const float4 bx = *reinterpret_cast<const float4*>(&t_sh[px + hoff]);
            const float4 by = *reinterpret_cast<const float4*>(&t_sh[py + hoff]);
            const float4 bz = *reinterpret_cast<const float4*>(&t_sh[pz + hoff]);
            const float4 bw = *reinterpret_cast<const float4*>(&t_sh[pw + hoff]);

            q[g*4+0].x += bx.x; q[g*4+0].y += by.x; q[g*4+0].z += bz.x; q[g*4+0].w += bw.x;
            q[g*4+1].x += bx.y; q[g*4+1].y += by.y; q[g*4+1].z += bz.y; q[g*4+1].w += bw.y;
            q[g*4+2].x += bx.z; q[g*4+2].y += by.z; q[g*4+2].z += bz.z; q[g*4+2].w += bw.z;
            q[g*4+3].x += bx.w; q[g*4+3].y += by.w; q[g*4+3].z += bz.w; q[g*4+3].w += bw.w;
        }

        #pragma unroll
        for (int j = 0; j < 8; j++) {
            __stcs(reinterpret_cast<float4*>(
                out + b0 + (size_t)j * PLS), q[j]);
        }
    }
}

extern "C" void kernel_launch(void* const* d_in, const int* in_sizes, int n_in,
                              void* d_out, int out_size) {
    const float* QK    = (const float*)d_in[0];
    const int*   pos   = (const int*)d_in[1];
    const float* table = (const float*)d_in[2];
    float* out = (float*)d_out;

    const int blocks = PN * PL;   // 4096
    gpe_kernel<<<blocks, 256>>>(QK, pos, table, out);
}